// round 9
// baseline (speedup 1.0000x reference)
#include <cuda_runtime.h>
#include <cuda_fp16.h>
#include <math.h>

#define BATCH 2
#define CCH   512
#define SEQ   4096
#define NH    8
#define HD    64
#define BH    (BATCH*NH)
#define WSZ   (CCH*CCH)

// fp16 scratch (allocation-free device globals)
__device__ __half g_tok[(size_t)BATCH * SEQ * CCH]; // [b][s][c]
__device__ __half g_w16[(size_t)4 * WSZ];           // Wq,Wk,Wv,Wp fp16 [o][c]
__device__ __half g_q16[(size_t)BH * SEQ * HD];     // [bh][s][d] (pre-scaled 0.125*log2e)
__device__ __half g_k16[(size_t)BH * SEQ * HD];     // [bh][s][d]
__device__ __half g_v16[(size_t)BH * HD * SEQ];     // [bh][d][s]
__device__ __half g_o16[(size_t)BATCH * SEQ * CCH]; // [b][s][c]

__device__ __forceinline__ unsigned pack2(float lo, float hi) {
    __half2 h = __floats2half2_rn(lo, hi);
    return *reinterpret_cast<unsigned*>(&h);
}
__device__ __forceinline__ unsigned ex2h2(float lo, float hi) {
    unsigned p = pack2(lo, hi), r;
    asm("ex2.approx.f16x2 %0, %1;" : "=r"(r) : "r"(p));
    return r;
}
__device__ __forceinline__ void mma16(float c[4], const unsigned a[4], const unsigned b[2]) {
    asm volatile(
        "mma.sync.aligned.m16n8k16.row.col.f32.f16.f16.f32 "
        "{%0,%1,%2,%3}, {%4,%5,%6,%7}, {%8,%9}, {%0,%1,%2,%3};\n"
        : "+f"(c[0]), "+f"(c[1]), "+f"(c[2]), "+f"(c[3])
        : "r"(a[0]), "r"(a[1]), "r"(a[2]), "r"(a[3]), "r"(b[0]), "r"(b[1]));
}
__device__ __forceinline__ void ldsm4(unsigned& r0, unsigned& r1, unsigned& r2, unsigned& r3,
                                      unsigned addr) {
    asm volatile("ldmatrix.sync.aligned.m8n8.x4.shared.b16 {%0,%1,%2,%3}, [%4];"
                 : "=r"(r0), "=r"(r1), "=r"(r2), "=r"(r3) : "r"(addr));
}
__device__ __forceinline__ void cp16(unsigned* smem_dst, const void* gmem_src) {
    unsigned sa = (unsigned)__cvta_generic_to_shared(smem_dst);
    asm volatile("cp.async.cg.shared.global [%0], [%1], 16;" :: "r"(sa), "l"(gmem_src));
}
#define CP_COMMIT() asm volatile("cp.async.commit_group;")
#define CP_WAIT1()  asm volatile("cp.async.wait_group 1;")

// ---------------------------------------------------------------------------
// Kernel 0a: transpose x [b][c][s] -> fp16 tok [b][s][c]
// ---------------------------------------------------------------------------
__global__ __launch_bounds__(256) void transpose_kernel(const float* __restrict__ x)
{
    __shared__ float tile[32][33];
    const int tx = threadIdx.x & 31, ty = threadIdx.x >> 5;
    const int s0 = blockIdx.x * 32, c0 = blockIdx.y * 32, b = blockIdx.z;
#pragma unroll
    for (int i = 0; i < 4; i++) {
        const int cl = ty + i * 8;
        tile[cl][tx] = x[((size_t)b * CCH + c0 + cl) * SEQ + s0 + tx];
    }
    __syncthreads();
#pragma unroll
    for (int i = 0; i < 4; i++) {
        const int sl = ty + i * 8;
        g_tok[((size_t)b * SEQ + s0 + sl) * CCH + c0 + tx] = __float2half_rn(tile[tx][sl]);
    }
}

// ---------------------------------------------------------------------------
// Kernel 0b: convert 4 weight matrices fp32 -> fp16 (row-major [o][c])
// ---------------------------------------------------------------------------
__global__ __launch_bounds__(256) void wconv_kernel(
    const float* __restrict__ Wq, const float* __restrict__ Wk,
    const float* __restrict__ Wv, const float* __restrict__ Wp)
{
    const int idx = blockIdx.x * 256 + threadIdx.x;
    const float* srcs[4] = {Wq, Wk, Wv, Wp};
    const int mi = idx >> 16;
    const int off = (idx & 65535) * 4;
    float4 v = *reinterpret_cast<const float4*>(srcs[mi] + off);
    *reinterpret_cast<uint2*>(&g_w16[(size_t)mi * WSZ + off]) =
        make_uint2(pack2(v.x, v.y), pack2(v.z, v.w));
}

// ---------------------------------------------------------------------------
// Kernel 1: QKV projections.  Tile 128(s) x 128(o), k=32, cp.async double buf,
// ldmatrix fragments.  Q written pre-scaled by 0.125*log2(e).
// ---------------------------------------------------------------------------
__shared__ unsigned qkv_sm[10240];   // As0|Bs0|As1|Bs1, each 128*20

__device__ __forceinline__ void stage_tile(unsigned* smA, unsigned* smB,
                                           const __half* aRow, const __half* bRow,
                                           int t, int k0)
{
#pragma unroll
    for (int u = 0; u < 2; u++) {
        int idx = t + u * 256;
        int r = idx >> 2, q4 = idx & 3;
        cp16(&smA[r * 20 + q4 * 4], aRow + (size_t)r * CCH + k0 + q4 * 8);
        cp16(&smB[r * 20 + q4 * 4], bRow + (size_t)r * CCH + k0 + q4 * 8);
    }
}

__global__ __launch_bounds__(256) void qkv_kernel(
    const float* __restrict__ bq, const float* __restrict__ bk,
    const float* __restrict__ bv)
{
    const int t = threadIdx.x;
    const int lane = t & 31, wid = t >> 5;
    const int g = lane >> 2, t4 = lane & 3;
    const int wm = wid & 3, wn = wid >> 2;
    const int s0 = blockIdx.x * 128;
    const int o0 = blockIdx.y * 128;
    const int z  = blockIdx.z;
    const int which = z % 3, b = z / 3;

    const float* bias = (which == 0) ? bq : (which == 1) ? bk : bv;
    const __half* aBase = g_tok + (size_t)b * SEQ * CCH + (size_t)s0 * CCH;
    const __half* bBase = g_w16 + (size_t)which * WSZ + (size_t)o0 * CCH;

    const int grp = lane >> 3, r8 = lane & 7;
    const unsigned sbase = (unsigned)__cvta_generic_to_shared(qkv_sm);
    const int aRowAdd = ((grp & 1) << 3) + r8;
    const unsigned aKoff = (grp & 2) ? 16u : 0u;
    const int bRowAdd = ((grp & 2) << 2) + r8;
    const unsigned bKoff = (grp & 1) ? 16u : 0u;

    float acc[2][8][4];
#pragma unroll
    for (int i = 0; i < 2; i++)
#pragma unroll
        for (int j = 0; j < 8; j++)
#pragma unroll
            for (int q = 0; q < 4; q++) acc[i][j][q] = 0.f;

    stage_tile(qkv_sm, qkv_sm + 2560, aBase, bBase, t, 0);
    CP_COMMIT();

    for (int kt = 0; kt < 16; kt++) {
        asm volatile("cp.async.wait_group 0;");
        __syncthreads();
        const int buf = kt & 1;
        if (kt < 15) {
            const int nbuf = (kt + 1) & 1;
            stage_tile(qkv_sm + nbuf * 5120, qkv_sm + nbuf * 5120 + 2560,
                       aBase, bBase, t, (kt + 1) * 32);
            CP_COMMIT();
        }
        const unsigned aB = sbase + (buf * 5120) * 4;
        const unsigned bB = sbase + (buf * 5120 + 2560) * 4;

#pragma unroll
        for (int kc = 0; kc < 2; kc++) {
            unsigned a[2][4];
#pragma unroll
            for (int tm = 0; tm < 2; tm++) {
                const int mrow = wm * 32 + tm * 16;
                ldsm4(a[tm][0], a[tm][1], a[tm][2], a[tm][3],
                      aB + (unsigned)(mrow + aRowAdd) * 80 + aKoff + kc * 32);
            }
#pragma unroll
            for (int p = 0; p < 4; p++) {
                unsigned b0, b1, b2, b3;
                const int nrow = wn * 64 + p * 16;
                ldsm4(b0, b1, b2, b3,
                      bB + (unsigned)(nrow + bRowAdd) * 80 + bKoff + kc * 32);
                unsigned bb0[2] = {b0, b1}, bb1[2] = {b2, b3};
#pragma unroll
                for (int tm = 0; tm < 2; tm++) {
                    mma16(acc[tm][2 * p],     a[tm], bb0);
                    mma16(acc[tm][2 * p + 1], a[tm], bb1);
                }
            }
        }
    }

    const float QSC = 0.125f * 1.44269504088896f;
#pragma unroll
    for (int tm = 0; tm < 2; tm++) {
#pragma unroll
        for (int tn = 0; tn < 8; tn++) {
            const int cg = o0 + wn * 64 + tn * 8 + 2 * t4;
            const int h  = cg >> 6;
            const int d  = cg & 63;
            const int bh = b * NH + h;
            const float b0 = bias[cg], b1 = bias[cg + 1];
#pragma unroll
            for (int half = 0; half < 2; half++) {
                const int s = s0 + wm * 32 + tm * 16 + g + half * 8;
                float v0 = acc[tm][tn][half * 2 + 0] + b0;
                float v1 = acc[tm][tn][half * 2 + 1] + b1;
                if (which == 0) {
                    v0 *= QSC; v1 *= QSC;
                    *reinterpret_cast<unsigned*>(
                        &g_q16[((size_t)bh * SEQ + s) * HD + d]) = pack2(v0, v1);
                } else if (which == 1) {
                    *reinterpret_cast<unsigned*>(
                        &g_k16[((size_t)bh * SEQ + s) * HD + d]) = pack2(v0, v1);
                } else {
                    g_v16[((size_t)bh * HD + d) * SEQ + s]     = __float2half_rn(v0);
                    g_v16[((size_t)bh * HD + d + 1) * SEQ + s] = __float2half_rn(v1);
                }
            }
        }
    }
}

// ---------------------------------------------------------------------------
// Kernel 2: flash attention, software-pipelined.
// Per iter: S(kt+1) mma, PV(kt) mma (back-to-back tensor bursts), then
// softmax(kt+1) ALU while pipe drains.  4-deep K/V ring, prefetch distance 3.
// smem: K ring 4x[64][36] + V ring 4x[64][36] = 73728 B.
// ---------------------------------------------------------------------------
extern __shared__ unsigned fa_sh[];

__device__ __forceinline__ void fa_stage(const __half* kP, const __half* vP, int j, int t)
{
    unsigned* Kd = fa_sh + (j & 3) * 2304;
    unsigned* Vd = fa_sh + 9216 + (j & 3) * 2304;
    const int koff = j * 64;
#pragma unroll
    for (int u = 0; u < 2; u++) {
        int idx = t + u * 256;
        int r = idx >> 3, ch = idx & 7;
        cp16(&Kd[r * 36 + ch * 4], kP + (size_t)(koff + r) * HD + ch * 8);
        cp16(&Vd[r * 36 + ch * 4], vP + (size_t)r * SEQ + koff + ch * 8);
    }
}

// softmax on s_f -> e01/e23, updates m/oacc/lacc (skip-rescale guard)
#define SOFTMAX_BLOCK()                                                        \
    do {                                                                       \
        float mx0 = -1e30f, mx1 = -1e30f;                                      \
        _Pragma("unroll")                                                      \
        for (int tn = 0; tn < 8; tn++) {                                       \
            mx0 = fmaxf(mx0, fmaxf(s_f[tn][0], s_f[tn][1]));                   \
            mx1 = fmaxf(mx1, fmaxf(s_f[tn][2], s_f[tn][3]));                   \
        }                                                                      \
        mx0 = fmaxf(mx0, __shfl_xor_sync(0xffffffffu, mx0, 1));                \
        mx0 = fmaxf(mx0, __shfl_xor_sync(0xffffffffu, mx0, 2));                \
        mx1 = fmaxf(mx1, __shfl_xor_sync(0xffffffffu, mx1, 1));                \
        mx1 = fmaxf(mx1, __shfl_xor_sync(0xffffffffu, mx1, 2));                \
        const bool up = (mx0 > m0) | (mx1 > m1);                               \
        const float nm0 = fmaxf(m0, mx0), nm1 = fmaxf(m1, mx1);                \
        if (__any_sync(0xffffffffu, up)) {                                     \
            const float al0 = exp2f(m0 - nm0), al1 = exp2f(m1 - nm1);          \
            _Pragma("unroll")                                                  \
            for (int tn = 0; tn < 8; tn++) {                                   \
                oacc[tn][0] *= al0; oacc[tn][1] *= al0;                        \
                oacc[tn][2] *= al1; oacc[tn][3] *= al1;                        \
            }                                                                  \
            lacc[0] *= al0; lacc[2] *= al1;                                    \
        }                                                                      \
        m0 = nm0; m1 = nm1;                                                    \
        _Pragma("unroll")                                                      \
        for (int tn = 0; tn < 8; tn++) {                                       \
            e01[tn] = ex2h2(s_f[tn][0] - nm0, s_f[tn][1] - nm0);               \
            e23[tn] = ex2h2(s_f[tn][2] - nm1, s_f[tn][3] - nm1);               \
        }                                                                      \
    } while (0)

__global__ void __launch_bounds__(256, 2) flash_kernel()
{
    const int t = threadIdx.x, lane = t & 31, wid = t >> 5;
    const int g = lane >> 2, t4 = lane & 3;
    const int bh = blockIdx.y, s0 = blockIdx.x * 128;
    const int b = bh >> 3, h = bh & 7;

    const unsigned* qU = reinterpret_cast<const unsigned*>(g_q16 + (size_t)bh * SEQ * HD);
    const __half*   kP = g_k16 + (size_t)bh * SEQ * HD;
    const __half*   vP = g_v16 + (size_t)bh * HD * SEQ;

    fa_stage(kP, vP, 0, t); CP_COMMIT();
    fa_stage(kP, vP, 1, t); CP_COMMIT();
    fa_stage(kP, vP, 2, t); CP_COMMIT();

    const int row = wid * 16 + g;
    unsigned qf[4][4];
#pragma unroll
    for (int kc = 0; kc < 4; kc++) {
        qf[kc][0] = qU[(size_t)(s0 + row) * 32 + kc * 8 + t4];
        qf[kc][1] = qU[(size_t)(s0 + row + 8) * 32 + kc * 8 + t4];
        qf[kc][2] = qU[(size_t)(s0 + row) * 32 + kc * 8 + t4 + 4];
        qf[kc][3] = qU[(size_t)(s0 + row + 8) * 32 + kc * 8 + t4 + 4];
    }

    const int grp = lane >> 3, r8 = lane & 7;
    const int nrow = r8 + ((grp & 2) ? 8 : 0);
    const unsigned lkoff = (grp & 1) ? 16u : 0u;
    const unsigned sbase = (unsigned)__cvta_generic_to_shared(fa_sh);
    const unsigned laddr = sbase + nrow * 144 + lkoff;   // + slot*9216 (+36864 for V)

    unsigned bbl[2];
    bbl[0] = bbl[1] = (g == 0) ? 0x3C003C00u : 0u;

    CP_WAIT1();
    __syncthreads();

    float m0 = -1e30f, m1 = -1e30f;
    float oacc[8][4], lacc[4];
#pragma unroll
    for (int i = 0; i < 8; i++)
#pragma unroll
        for (int j = 0; j < 4; j++) oacc[i][j] = 0.f;
#pragma unroll
    for (int j = 0; j < 4; j++) lacc[j] = 0.f;

    float s_f[8][4];
    unsigned e01[8], e23[8];

    // ---- prologue: S(0) + softmax(0) ----
#pragma unroll
    for (int i = 0; i < 8; i++)
#pragma unroll
        for (int j = 0; j < 4; j++) s_f[i][j] = 0.f;
    {
        const unsigned kB = laddr;   // slot 0
#pragma unroll
        for (int kc = 0; kc < 4; kc++)
#pragma unroll
            for (int p = 0; p < 4; p++) {
                unsigned b0, b1, b2, b3;
                ldsm4(b0, b1, b2, b3, kB + p * 2304 + kc * 32);
                unsigned bb0[2] = {b0, b1}, bb1[2] = {b2, b3};
                mma16(s_f[2 * p],     qf[kc], bb0);
                mma16(s_f[2 * p + 1], qf[kc], bb1);
            }
    }
    SOFTMAX_BLOCK();

    // ---- main loop ----
    for (int kt = 0; kt < 64; kt++) {
        if (kt < 61) fa_stage(kP, vP, kt + 3, t);
        CP_COMMIT();

        // S(kt+1): tensor burst #1
        if (kt < 63) {
#pragma unroll
            for (int i = 0; i < 8; i++)
#pragma unroll
                for (int j = 0; j < 4; j++) s_f[i][j] = 0.f;
            const unsigned kB = laddr + ((kt + 1) & 3) * 9216;
#pragma unroll
            for (int kc = 0; kc < 4; kc++)
#pragma unroll
                for (int p = 0; p < 4; p++) {
                    unsigned b0, b1, b2, b3;
                    ldsm4(b0, b1, b2, b3, kB + p * 2304 + kc * 32);
                    unsigned bb0[2] = {b0, b1}, bb1[2] = {b2, b3};
                    mma16(s_f[2 * p],     qf[kc], bb0);
                    mma16(s_f[2 * p + 1], qf[kc], bb1);
                }
        }

        // PV(kt): tensor burst #2 (uses e from softmax(kt))
        {
            const unsigned vB = laddr + 36864u + (kt & 3) * 9216;
#pragma unroll
            for (int kc = 0; kc < 4; kc++) {
                unsigned a[4];
                a[0] = e01[2 * kc];     a[1] = e23[2 * kc];
                a[2] = e01[2 * kc + 1]; a[3] = e23[2 * kc + 1];
#pragma unroll
                for (int p = 0; p < 4; p++) {
                    unsigned b0, b1, b2, b3;
                    ldsm4(b0, b1, b2, b3, vB + p * 2304 + kc * 32);
                    unsigned bb0[2] = {b0, b1}, bb1[2] = {b2, b3};
                    mma16(oacc[2 * p],     a, bb0);
                    mma16(oacc[2 * p + 1], a, bb1);
                }
                mma16(lacc, a, bbl);
            }
        }

        // softmax(kt+1) — ALU work while tensor pipe drains
        if (kt < 63) {
            SOFTMAX_BLOCK();
            CP_WAIT1();
            __syncthreads();
        }
    }

    // ---- epilogue ----
    const float l0 = __shfl_sync(0xffffffffu, lacc[0], lane & 28);
    const float l1 = __shfl_sync(0xffffffffu, lacc[2], lane & 28);
    const float r0 = 1.f / l0, r1 = 1.f / l1;
    const int srow = s0 + row;
#pragma unroll
    for (int tn = 0; tn < 8; tn++) {
        const int c = h * 64 + tn * 8 + 2 * t4;
        *reinterpret_cast<unsigned*>(&g_o16[((size_t)b * SEQ + srow) * CCH + c]) =
            pack2(oacc[tn][0] * r0, oacc[tn][1] * r0);
        *reinterpret_cast<unsigned*>(&g_o16[((size_t)b * SEQ + srow + 8) * CCH + c]) =
            pack2(oacc[tn][2] * r1, oacc[tn][3] * r1);
    }
}

// ---------------------------------------------------------------------------
// Kernel 3: out-projection.  Same pipelined structure as qkv.
// ---------------------------------------------------------------------------
__shared__ unsigned proj_sm[10240];

__global__ __launch_bounds__(256) void proj_kernel(
    const float* __restrict__ bp, float* __restrict__ out)
{
    const int t = threadIdx.x;
    const int lane = t & 31, wid = t >> 5;
    const int g = lane >> 2, t4 = lane & 3;
    const int wm = wid & 3, wn = wid >> 2;
    const int s0 = blockIdx.x * 128;
    const int o0 = blockIdx.y * 128;
    const int b  = blockIdx.z;

    const __half* aBase = g_o16 + (size_t)b * SEQ * CCH + (size_t)s0 * CCH;
    const __half* bBase = g_w16 + (size_t)3 * WSZ + (size_t)o0 * CCH;

    const int grp = lane >> 3, r8 = lane & 7;
    const unsigned sbase = (unsigned)__cvta_generic_to_shared(proj_sm);
    const int aRowAdd = ((grp & 1) << 3) + r8;
    const unsigned aKoff = (grp & 2) ? 16u : 0u;
    const int bRowAdd = ((grp & 2) << 2) + r8;
    const unsigned bKoff = (grp & 1) ? 16u : 0u;

    float acc[2][8][4];
#pragma unroll
    for (int i = 0; i < 2; i++)
#pragma unroll
        for (int j = 0; j < 8; j++)
#pragma unroll
            for (int q = 0; q < 4; q++) acc[i][j][q] = 0.f;

    stage_tile(proj_sm, proj_sm + 2560, aBase, bBase, t, 0);
    CP_COMMIT();

    for (int kt = 0; kt < 16; kt++) {
        asm volatile("cp.async.wait_group 0;");
        __syncthreads();
        const int buf = kt & 1;
        if (kt < 15) {
            const int nbuf = (kt + 1) & 1;
            stage_tile(proj_sm + nbuf * 5120, proj_sm + nbuf * 5120 + 2560,
                       aBase, bBase, t, (kt + 1) * 32);
            CP_COMMIT();
        }
        const unsigned aB = sbase + (buf * 5120) * 4;
        const unsigned bB = sbase + (buf * 5120 + 2560) * 4;

#pragma unroll
        for (int kc = 0; kc < 2; kc++) {
            unsigned a[2][4];
#pragma unroll
            for (int tm = 0; tm < 2; tm++) {
                const int mrow = wm * 32 + tm * 16;
                ldsm4(a[tm][0], a[tm][1], a[tm][2], a[tm][3],
                      aB + (unsigned)(mrow + aRowAdd) * 80 + aKoff + kc * 32);
            }
#pragma unroll
            for (int p = 0; p < 4; p++) {
                unsigned b0, b1, b2, b3;
                const int nrow = wn * 64 + p * 16;
                ldsm4(b0, b1, b2, b3,
                      bB + (unsigned)(nrow + bRowAdd) * 80 + bKoff + kc * 32);
                unsigned bb0[2] = {b0, b1}, bb1[2] = {b2, b3};
#pragma unroll
                for (int tm = 0; tm < 2; tm++) {
                    mma16(acc[tm][2 * p],     a[tm], bb0);
                    mma16(acc[tm][2 * p + 1], a[tm], bb1);
                }
            }
        }
    }

#pragma unroll
    for (int tm = 0; tm < 2; tm++) {
#pragma unroll
        for (int tn = 0; tn < 8; tn++) {
            const int col0 = o0 + wn * 64 + tn * 8 + 2 * t4;
            const float b0 = bp[col0], b1 = bp[col0 + 1];
#pragma unroll
            for (int half = 0; half < 2; half++) {
                const int s = s0 + wm * 32 + tm * 16 + g + half * 8;
                out[((size_t)b * CCH + col0) * SEQ + s]     = acc[tm][tn][half * 2 + 0] + b0;
                out[((size_t)b * CCH + col0 + 1) * SEQ + s] = acc[tm][tn][half * 2 + 1] + b1;
            }
        }
    }
}

// ---------------------------------------------------------------------------
extern "C" void kernel_launch(void* const* d_in, const int* in_sizes, int n_in,
                              void* d_out, int out_size)
{
    const float* x  = (const float*)d_in[0];
    const float* Wq = (const float*)d_in[1];
    const float* bq = (const float*)d_in[2];
    const float* Wk = (const float*)d_in[3];
    const float* bk = (const float*)d_in[4];
    const float* Wv = (const float*)d_in[5];
    const float* bv = (const float*)d_in[6];
    const float* Wp = (const float*)d_in[7];
    const float* bp = (const float*)d_in[8];
    float* out = (float*)d_out;

    const int FA_SMEM = 8 * 2304 * 4;  // 73728 B
    cudaFuncSetAttribute(flash_kernel,
                         cudaFuncAttributeMaxDynamicSharedMemorySize, FA_SMEM);

    transpose_kernel<<<dim3(SEQ / 32, CCH / 32, BATCH), 256>>>(x);
    wconv_kernel<<<1024, 256>>>(Wq, Wk, Wv, Wp);
    qkv_kernel<<<dim3(SEQ / 128, CCH / 128, 3 * BATCH), 256>>>(bq, bk, bv);
    flash_kernel<<<dim3(SEQ / 128, BH), 256, FA_SMEM>>>();
    proj_kernel<<<dim3(SEQ / 128, CCH / 128, BATCH), 256>>>(bp, out);
}

// round 10
// speedup vs baseline: 1.1093x; 1.1093x over previous
#include <cuda_runtime.h>
#include <cuda_fp16.h>
#include <math.h>

#define BATCH 2
#define CCH   512
#define SEQ   4096
#define NH    8
#define HD    64
#define BH    (BATCH*NH)
#define WSZ   (CCH*CCH)

// fp16 scratch (allocation-free device globals)
__device__ __half g_tok[(size_t)BATCH * SEQ * CCH]; // [b][s][c]
__device__ __half g_w16[(size_t)4 * WSZ];           // Wq,Wk,Wv,Wp fp16 [o][c]
__device__ __half g_q16[(size_t)BH * SEQ * HD];     // [bh][s][d] (pre-scaled 0.125*log2e)
__device__ __half g_k16[(size_t)BH * SEQ * HD];     // [bh][s][d]
__device__ __half g_v16[(size_t)BH * HD * SEQ];     // [bh][d][s]
__device__ __half g_o16[(size_t)BATCH * SEQ * CCH]; // [b][s][c]

__device__ __forceinline__ unsigned pack2(float lo, float hi) {
    __half2 h = __floats2half2_rn(lo, hi);
    return *reinterpret_cast<unsigned*>(&h);
}
__device__ __forceinline__ unsigned ex2h2(float lo, float hi) {
    unsigned p = pack2(lo, hi), r;
    asm("ex2.approx.f16x2 %0, %1;" : "=r"(r) : "r"(p));
    return r;
}
__device__ __forceinline__ void mma16(float c[4], const unsigned a[4], const unsigned b[2]) {
    asm volatile(
        "mma.sync.aligned.m16n8k16.row.col.f32.f16.f16.f32 "
        "{%0,%1,%2,%3}, {%4,%5,%6,%7}, {%8,%9}, {%0,%1,%2,%3};\n"
        : "+f"(c[0]), "+f"(c[1]), "+f"(c[2]), "+f"(c[3])
        : "r"(a[0]), "r"(a[1]), "r"(a[2]), "r"(a[3]), "r"(b[0]), "r"(b[1]));
}
__device__ __forceinline__ void ldsm4(unsigned& r0, unsigned& r1, unsigned& r2, unsigned& r3,
                                      unsigned addr) {
    asm volatile("ldmatrix.sync.aligned.m8n8.x4.shared.b16 {%0,%1,%2,%3}, [%4];"
                 : "=r"(r0), "=r"(r1), "=r"(r2), "=r"(r3) : "r"(addr));
}
__device__ __forceinline__ void cp16(unsigned* smem_dst, const void* gmem_src) {
    unsigned sa = (unsigned)__cvta_generic_to_shared(smem_dst);
    asm volatile("cp.async.cg.shared.global [%0], [%1], 16;" :: "r"(sa), "l"(gmem_src));
}
#define CP_COMMIT() asm volatile("cp.async.commit_group;")

// ---- mbarrier helpers ----
__device__ __forceinline__ unsigned smem_u32p(const void* p) {
    return (unsigned)__cvta_generic_to_shared(p);
}
__device__ __forceinline__ void mbar_init(unsigned addr, unsigned cnt) {
    asm volatile("mbarrier.init.shared.b64 [%0], %1;" :: "r"(addr), "r"(cnt) : "memory");
}
__device__ __forceinline__ void mbar_arrive(unsigned addr) {
    asm volatile("mbarrier.arrive.shared.b64 _, [%0];" :: "r"(addr) : "memory");
}
__device__ __forceinline__ void mbar_wait(unsigned addr, unsigned parity) {
    asm volatile(
        "{\n\t"
        ".reg .pred P1;\n\t"
        "LAB_WAIT_%=:\n\t"
        "mbarrier.try_wait.parity.acquire.cta.shared::cta.b64 P1, [%0], %1, 0x989680;\n\t"
        "@P1 bra.uni LAB_DONE_%=;\n\t"
        "bra.uni LAB_WAIT_%=;\n\t"
        "LAB_DONE_%=:\n\t"
        "}"
        :: "r"(addr), "r"(parity) : "memory");
}
__device__ __forceinline__ void cpasync_arrive_noinc(unsigned addr) {
    asm volatile("cp.async.mbarrier.arrive.noinc.shared.b64 [%0];" :: "r"(addr) : "memory");
}

// ---------------------------------------------------------------------------
// Kernel 0a: transpose x [b][c][s] -> fp16 tok [b][s][c]
// ---------------------------------------------------------------------------
__global__ __launch_bounds__(256) void transpose_kernel(const float* __restrict__ x)
{
    __shared__ float tile[32][33];
    const int tx = threadIdx.x & 31, ty = threadIdx.x >> 5;
    const int s0 = blockIdx.x * 32, c0 = blockIdx.y * 32, b = blockIdx.z;
#pragma unroll
    for (int i = 0; i < 4; i++) {
        const int cl = ty + i * 8;
        tile[cl][tx] = x[((size_t)b * CCH + c0 + cl) * SEQ + s0 + tx];
    }
    __syncthreads();
#pragma unroll
    for (int i = 0; i < 4; i++) {
        const int sl = ty + i * 8;
        g_tok[((size_t)b * SEQ + s0 + sl) * CCH + c0 + tx] = __float2half_rn(tile[tx][sl]);
    }
}

// ---------------------------------------------------------------------------
// Kernel 0b: convert 4 weight matrices fp32 -> fp16 (row-major [o][c])
// ---------------------------------------------------------------------------
__global__ __launch_bounds__(256) void wconv_kernel(
    const float* __restrict__ Wq, const float* __restrict__ Wk,
    const float* __restrict__ Wv, const float* __restrict__ Wp)
{
    const int idx = blockIdx.x * 256 + threadIdx.x;
    const float* srcs[4] = {Wq, Wk, Wv, Wp};
    const int mi = idx >> 16;
    const int off = (idx & 65535) * 4;
    float4 v = *reinterpret_cast<const float4*>(srcs[mi] + off);
    *reinterpret_cast<uint2*>(&g_w16[(size_t)mi * WSZ + off]) =
        make_uint2(pack2(v.x, v.y), pack2(v.z, v.w));
}

// ---------------------------------------------------------------------------
// Kernel 1: QKV projections.  Tile 128(s) x 128(o), k=32, cp.async double buf,
// ldmatrix fragments.  Q written pre-scaled by 0.125*log2(e).
// ---------------------------------------------------------------------------
__shared__ unsigned qkv_sm[10240];   // As0|Bs0|As1|Bs1, each 128*20

__device__ __forceinline__ void stage_tile(unsigned* smA, unsigned* smB,
                                           const __half* aRow, const __half* bRow,
                                           int t, int k0)
{
#pragma unroll
    for (int u = 0; u < 2; u++) {
        int idx = t + u * 256;
        int r = idx >> 2, q4 = idx & 3;
        cp16(&smA[r * 20 + q4 * 4], aRow + (size_t)r * CCH + k0 + q4 * 8);
        cp16(&smB[r * 20 + q4 * 4], bRow + (size_t)r * CCH + k0 + q4 * 8);
    }
}

__global__ __launch_bounds__(256) void qkv_kernel(
    const float* __restrict__ bq, const float* __restrict__ bk,
    const float* __restrict__ bv)
{
    const int t = threadIdx.x;
    const int lane = t & 31, wid = t >> 5;
    const int g = lane >> 2, t4 = lane & 3;
    const int wm = wid & 3, wn = wid >> 2;
    const int s0 = blockIdx.x * 128;
    const int o0 = blockIdx.y * 128;
    const int z  = blockIdx.z;
    const int which = z % 3, b = z / 3;

    const float* bias = (which == 0) ? bq : (which == 1) ? bk : bv;
    const __half* aBase = g_tok + (size_t)b * SEQ * CCH + (size_t)s0 * CCH;
    const __half* bBase = g_w16 + (size_t)which * WSZ + (size_t)o0 * CCH;

    const int grp = lane >> 3, r8 = lane & 7;
    const unsigned sbase = (unsigned)__cvta_generic_to_shared(qkv_sm);
    const int aRowAdd = ((grp & 1) << 3) + r8;
    const unsigned aKoff = (grp & 2) ? 16u : 0u;
    const int bRowAdd = ((grp & 2) << 2) + r8;
    const unsigned bKoff = (grp & 1) ? 16u : 0u;

    float acc[2][8][4];
#pragma unroll
    for (int i = 0; i < 2; i++)
#pragma unroll
        for (int j = 0; j < 8; j++)
#pragma unroll
            for (int q = 0; q < 4; q++) acc[i][j][q] = 0.f;

    stage_tile(qkv_sm, qkv_sm + 2560, aBase, bBase, t, 0);
    CP_COMMIT();

    for (int kt = 0; kt < 16; kt++) {
        asm volatile("cp.async.wait_group 0;");
        __syncthreads();
        const int buf = kt & 1;
        if (kt < 15) {
            const int nbuf = (kt + 1) & 1;
            stage_tile(qkv_sm + nbuf * 5120, qkv_sm + nbuf * 5120 + 2560,
                       aBase, bBase, t, (kt + 1) * 32);
            CP_COMMIT();
        }
        const unsigned aB = sbase + (buf * 5120) * 4;
        const unsigned bB = sbase + (buf * 5120 + 2560) * 4;

#pragma unroll
        for (int kc = 0; kc < 2; kc++) {
            unsigned a[2][4];
#pragma unroll
            for (int tm = 0; tm < 2; tm++) {
                const int mrow = wm * 32 + tm * 16;
                ldsm4(a[tm][0], a[tm][1], a[tm][2], a[tm][3],
                      aB + (unsigned)(mrow + aRowAdd) * 80 + aKoff + kc * 32);
            }
#pragma unroll
            for (int p = 0; p < 4; p++) {
                unsigned b0, b1, b2, b3;
                const int nrow = wn * 64 + p * 16;
                ldsm4(b0, b1, b2, b3,
                      bB + (unsigned)(nrow + bRowAdd) * 80 + bKoff + kc * 32);
                unsigned bb0[2] = {b0, b1}, bb1[2] = {b2, b3};
#pragma unroll
                for (int tm = 0; tm < 2; tm++) {
                    mma16(acc[tm][2 * p],     a[tm], bb0);
                    mma16(acc[tm][2 * p + 1], a[tm], bb1);
                }
            }
        }
    }

    const float QSC = 0.125f * 1.44269504088896f;
#pragma unroll
    for (int tm = 0; tm < 2; tm++) {
#pragma unroll
        for (int tn = 0; tn < 8; tn++) {
            const int cg = o0 + wn * 64 + tn * 8 + 2 * t4;
            const int h  = cg >> 6;
            const int d  = cg & 63;
            const int bh = b * NH + h;
            const float b0 = bias[cg], b1 = bias[cg + 1];
#pragma unroll
            for (int half = 0; half < 2; half++) {
                const int s = s0 + wm * 32 + tm * 16 + g + half * 8;
                float v0 = acc[tm][tn][half * 2 + 0] + b0;
                float v1 = acc[tm][tn][half * 2 + 1] + b1;
                if (which == 0) {
                    v0 *= QSC; v1 *= QSC;
                    *reinterpret_cast<unsigned*>(
                        &g_q16[((size_t)bh * SEQ + s) * HD + d]) = pack2(v0, v1);
                } else if (which == 1) {
                    *reinterpret_cast<unsigned*>(
                        &g_k16[((size_t)bh * SEQ + s) * HD + d]) = pack2(v0, v1);
                } else {
                    g_v16[((size_t)bh * HD + d) * SEQ + s]     = __float2half_rn(v0);
                    g_v16[((size_t)bh * HD + d + 1) * SEQ + s] = __float2half_rn(v1);
                }
            }
        }
    }
}

// ---------------------------------------------------------------------------
// Kernel 2: flash attention, free-running mbarrier pipeline (no __syncthreads
// in the loop -> warps drift, softmax of one warp overlaps mma of others).
// 4-slot K/V ring: slot j = K[64][36] + V[64][36] at fa_sh + j*4608 uints.
// full[j]: 256 cp.async completions; empty[j]: 256 consumer arrivals.
// ---------------------------------------------------------------------------
extern __shared__ unsigned fa_sh[];

__device__ __forceinline__ void fa_stage(const __half* kP, const __half* vP, int j, int t)
{
    unsigned* Kd = fa_sh + (j & 3) * 4608;
    unsigned* Vd = Kd + 2304;
    const int koff = j * 64;
#pragma unroll
    for (int u = 0; u < 2; u++) {
        int idx = t + u * 256;
        int r = idx >> 3, ch = idx & 7;
        cp16(&Kd[r * 36 + ch * 4], kP + (size_t)(koff + r) * HD + ch * 8);
        cp16(&Vd[r * 36 + ch * 4], vP + (size_t)r * SEQ + koff + ch * 8);
    }
}

#define SOFTMAX_BLOCK()                                                        \
    do {                                                                       \
        float mx0 = -1e30f, mx1 = -1e30f;                                      \
        _Pragma("unroll")                                                      \
        for (int tn = 0; tn < 8; tn++) {                                       \
            mx0 = fmaxf(mx0, fmaxf(s_f[tn][0], s_f[tn][1]));                   \
            mx1 = fmaxf(mx1, fmaxf(s_f[tn][2], s_f[tn][3]));                   \
        }                                                                      \
        mx0 = fmaxf(mx0, __shfl_xor_sync(0xffffffffu, mx0, 1));                \
        mx0 = fmaxf(mx0, __shfl_xor_sync(0xffffffffu, mx0, 2));                \
        mx1 = fmaxf(mx1, __shfl_xor_sync(0xffffffffu, mx1, 1));                \
        mx1 = fmaxf(mx1, __shfl_xor_sync(0xffffffffu, mx1, 2));                \
        const bool up = (mx0 > m0) | (mx1 > m1);                               \
        const float nm0 = fmaxf(m0, mx0), nm1 = fmaxf(m1, mx1);                \
        if (__any_sync(0xffffffffu, up)) {                                     \
            const float al0 = exp2f(m0 - nm0), al1 = exp2f(m1 - nm1);          \
            _Pragma("unroll")                                                  \
            for (int tn = 0; tn < 8; tn++) {                                   \
                oacc[tn][0] *= al0; oacc[tn][1] *= al0;                        \
                oacc[tn][2] *= al1; oacc[tn][3] *= al1;                        \
            }                                                                  \
            lacc[0] *= al0; lacc[2] *= al1;                                    \
        }                                                                      \
        m0 = nm0; m1 = nm1;                                                    \
        _Pragma("unroll")                                                      \
        for (int tn = 0; tn < 8; tn++) {                                       \
            e01[tn] = ex2h2(s_f[tn][0] - nm0, s_f[tn][1] - nm0);               \
            e23[tn] = ex2h2(s_f[tn][2] - nm1, s_f[tn][3] - nm1);               \
        }                                                                      \
    } while (0)

__global__ void __launch_bounds__(256, 2) flash_kernel()
{
    __shared__ __align__(8) unsigned long long fa_mbar[8];  // full[0..3], empty[4..7]

    const int t = threadIdx.x, lane = t & 31, wid = t >> 5;
    const int g = lane >> 2, t4 = lane & 3;
    const int bh = blockIdx.y, s0 = blockIdx.x * 128;
    const int b = bh >> 3, h = bh & 7;

    const unsigned* qU = reinterpret_cast<const unsigned*>(g_q16 + (size_t)bh * SEQ * HD);
    const __half*   kP = g_k16 + (size_t)bh * SEQ * HD;
    const __half*   vP = g_v16 + (size_t)bh * HD * SEQ;

    const unsigned mb0 = smem_u32p(fa_mbar);
    if (t == 0) {
#pragma unroll
        for (int j = 0; j < 8; j++) mbar_init(mb0 + j * 8, 256);
    }
    __syncthreads();

    // ---- prologue: stage tiles 0..2, arrive full[0..2] ----
    fa_stage(kP, vP, 0, t); cpasync_arrive_noinc(mb0 + 0 * 8);
    fa_stage(kP, vP, 1, t); cpasync_arrive_noinc(mb0 + 1 * 8);
    fa_stage(kP, vP, 2, t); cpasync_arrive_noinc(mb0 + 2 * 8);

    // Q fragments from gmem (already scaled)
    const int row = wid * 16 + g;
    unsigned qf[4][4];
#pragma unroll
    for (int kc = 0; kc < 4; kc++) {
        qf[kc][0] = qU[(size_t)(s0 + row) * 32 + kc * 8 + t4];
        qf[kc][1] = qU[(size_t)(s0 + row + 8) * 32 + kc * 8 + t4];
        qf[kc][2] = qU[(size_t)(s0 + row) * 32 + kc * 8 + t4 + 4];
        qf[kc][3] = qU[(size_t)(s0 + row + 8) * 32 + kc * 8 + t4 + 4];
    }

    const int grp = lane >> 3, r8 = lane & 7;
    const int nrow = r8 + ((grp & 2) ? 8 : 0);
    const unsigned lkoff = (grp & 1) ? 16u : 0u;
    const unsigned sbase = (unsigned)__cvta_generic_to_shared(fa_sh);
    const unsigned laddr = sbase + nrow * 144 + lkoff;   // + slot*18432 (K), +9216 (V)

    unsigned bbl[2];
    bbl[0] = bbl[1] = (g == 0) ? 0x3C003C00u : 0u;

    float m0 = -1e30f, m1 = -1e30f;
    float oacc[8][4], lacc[4];
#pragma unroll
    for (int i = 0; i < 8; i++)
#pragma unroll
        for (int j = 0; j < 4; j++) oacc[i][j] = 0.f;
#pragma unroll
    for (int j = 0; j < 4; j++) lacc[j] = 0.f;

    float s_f[8][4];
    unsigned e01[8], e23[8];

    for (int kt = 0; kt < 64; kt++) {
        // ---- producer: stage tile kt+3 into slot (kt+3)&3 ----
        const int jt = kt + 3;
        if (jt < 64) {
            const int f = jt >> 2;   // fill index of this slot
            if (f >= 1)
                mbar_wait(mb0 + (4 + (jt & 3)) * 8, (unsigned)((f - 1) & 1));
            fa_stage(kP, vP, jt, t);
            cpasync_arrive_noinc(mb0 + (jt & 3) * 8);
        }

        // ---- consumer: wait slot kt&3 full ----
        mbar_wait(mb0 + (kt & 3) * 8, (unsigned)((kt >> 2) & 1));
        const unsigned kB = laddr + (unsigned)(kt & 3) * 18432u;
        const unsigned vB = kB + 9216u;

        // ---- S = Q K^T (log2 domain, pre-scaled) ----
#pragma unroll
        for (int i = 0; i < 8; i++)
#pragma unroll
            for (int j = 0; j < 4; j++) s_f[i][j] = 0.f;
#pragma unroll
        for (int kc = 0; kc < 4; kc++)
#pragma unroll
            for (int p = 0; p < 4; p++) {
                unsigned b0, b1, b2, b3;
                ldsm4(b0, b1, b2, b3, kB + p * 2304 + kc * 32);
                unsigned bb0[2] = {b0, b1}, bb1[2] = {b2, b3};
                mma16(s_f[2 * p],     qf[kc], bb0);
                mma16(s_f[2 * p + 1], qf[kc], bb1);
            }

        // ---- online softmax ----
        SOFTMAX_BLOCK();

        // ---- O += P V ; l += P 1 ----
#pragma unroll
        for (int kc = 0; kc < 4; kc++) {
            unsigned a[4];
            a[0] = e01[2 * kc];     a[1] = e23[2 * kc];
            a[2] = e01[2 * kc + 1]; a[3] = e23[2 * kc + 1];
#pragma unroll
            for (int p = 0; p < 4; p++) {
                unsigned b0, b1, b2, b3;
                ldsm4(b0, b1, b2, b3, vB + p * 2304 + kc * 32);
                unsigned bb0[2] = {b0, b1}, bb1[2] = {b2, b3};
                mma16(oacc[2 * p],     a, bb0);
                mma16(oacc[2 * p + 1], a, bb1);
            }
            mma16(lacc, a, bbl);
        }

        // ---- consumer done with slot ----
        mbar_arrive(mb0 + (4 + (kt & 3)) * 8);
    }

    // ---- epilogue ----
    const float l0 = __shfl_sync(0xffffffffu, lacc[0], lane & 28);
    const float l1 = __shfl_sync(0xffffffffu, lacc[2], lane & 28);
    const float r0 = 1.f / l0, r1 = 1.f / l1;
    const int srow = s0 + row;
#pragma unroll
    for (int tn = 0; tn < 8; tn++) {
        const int c = h * 64 + tn * 8 + 2 * t4;
        *reinterpret_cast<unsigned*>(&g_o16[((size_t)b * SEQ + srow) * CCH + c]) =
            pack2(oacc[tn][0] * r0, oacc[tn][1] * r0);
        *reinterpret_cast<unsigned*>(&g_o16[((size_t)b * SEQ + srow + 8) * CCH + c]) =
            pack2(oacc[tn][2] * r1, oacc[tn][3] * r1);
    }
}

// ---------------------------------------------------------------------------
// Kernel 3: out-projection.  Same pipelined structure as qkv.
// ---------------------------------------------------------------------------
__shared__ unsigned proj_sm[10240];

__global__ __launch_bounds__(256) void proj_kernel(
    const float* __restrict__ bp, float* __restrict__ out)
{
    const int t = threadIdx.x;
    const int lane = t & 31, wid = t >> 5;
    const int g = lane >> 2, t4 = lane & 3;
    const int wm = wid & 3, wn = wid >> 2;
    const int s0 = blockIdx.x * 128;
    const int o0 = blockIdx.y * 128;
    const int b  = blockIdx.z;

    const __half* aBase = g_o16 + (size_t)b * SEQ * CCH + (size_t)s0 * CCH;
    const __half* bBase = g_w16 + (size_t)3 * WSZ + (size_t)o0 * CCH;

    const int grp = lane >> 3, r8 = lane & 7;
    const unsigned sbase = (unsigned)__cvta_generic_to_shared(proj_sm);
    const int aRowAdd = ((grp & 1) << 3) + r8;
    const unsigned aKoff = (grp & 2) ? 16u : 0u;
    const int bRowAdd = ((grp & 2) << 2) + r8;
    const unsigned bKoff = (grp & 1) ? 16u : 0u;

    float acc[2][8][4];
#pragma unroll
    for (int i = 0; i < 2; i++)
#pragma unroll
        for (int j = 0; j < 8; j++)
#pragma unroll
            for (int q = 0; q < 4; q++) acc[i][j][q] = 0.f;

    stage_tile(proj_sm, proj_sm + 2560, aBase, bBase, t, 0);
    CP_COMMIT();

    for (int kt = 0; kt < 16; kt++) {
        asm volatile("cp.async.wait_group 0;");
        __syncthreads();
        const int buf = kt & 1;
        if (kt < 15) {
            const int nbuf = (kt + 1) & 1;
            stage_tile(proj_sm + nbuf * 5120, proj_sm + nbuf * 5120 + 2560,
                       aBase, bBase, t, (kt + 1) * 32);
            CP_COMMIT();
        }
        const unsigned aB = sbase + (buf * 5120) * 4;
        const unsigned bB = sbase + (buf * 5120 + 2560) * 4;

#pragma unroll
        for (int kc = 0; kc < 2; kc++) {
            unsigned a[2][4];
#pragma unroll
            for (int tm = 0; tm < 2; tm++) {
                const int mrow = wm * 32 + tm * 16;
                ldsm4(a[tm][0], a[tm][1], a[tm][2], a[tm][3],
                      aB + (unsigned)(mrow + aRowAdd) * 80 + aKoff + kc * 32);
            }
#pragma unroll
            for (int p = 0; p < 4; p++) {
                unsigned b0, b1, b2, b3;
                const int nrow = wn * 64 + p * 16;
                ldsm4(b0, b1, b2, b3,
                      bB + (unsigned)(nrow + bRowAdd) * 80 + bKoff + kc * 32);
                unsigned bb0[2] = {b0, b1}, bb1[2] = {b2, b3};
#pragma unroll
                for (int tm = 0; tm < 2; tm++) {
                    mma16(acc[tm][2 * p],     a[tm], bb0);
                    mma16(acc[tm][2 * p + 1], a[tm], bb1);
                }
            }
        }
    }

#pragma unroll
    for (int tm = 0; tm < 2; tm++) {
#pragma unroll
        for (int tn = 0; tn < 8; tn++) {
            const int col0 = o0 + wn * 64 + tn * 8 + 2 * t4;
            const float b0 = bp[col0], b1 = bp[col0 + 1];
#pragma unroll
            for (int half = 0; half < 2; half++) {
                const int s = s0 + wm * 32 + tm * 16 + g + half * 8;
                out[((size_t)b * CCH + col0) * SEQ + s]     = acc[tm][tn][half * 2 + 0] + b0;
                out[((size_t)b * CCH + col0 + 1) * SEQ + s] = acc[tm][tn][half * 2 + 1] + b1;
            }
        }
    }
}

// ---------------------------------------------------------------------------
extern "C" void kernel_launch(void* const* d_in, const int* in_sizes, int n_in,
                              void* d_out, int out_size)
{
    const float* x  = (const float*)d_in[0];
    const float* Wq = (const float*)d_in[1];
    const float* bq = (const float*)d_in[2];
    const float* Wk = (const float*)d_in[3];
    const float* bk = (const float*)d_in[4];
    const float* Wv = (const float*)d_in[5];
    const float* bv = (const float*)d_in[6];
    const float* Wp = (const float*)d_in[7];
    const float* bp = (const float*)d_in[8];
    float* out = (float*)d_out;

    const int FA_SMEM = 4 * 4608 * 4;  // 73728 B (4 slots x (K+V))
    cudaFuncSetAttribute(flash_kernel,
                         cudaFuncAttributeMaxDynamicSharedMemorySize, FA_SMEM);

    transpose_kernel<<<dim3(SEQ / 32, CCH / 32, BATCH), 256>>>(x);
    wconv_kernel<<<1024, 256>>>(Wq, Wk, Wv, Wp);
    qkv_kernel<<<dim3(SEQ / 128, CCH / 128, 3 * BATCH), 256>>>(bq, bk, bv);
    flash_kernel<<<dim3(SEQ / 128, BH), 256, FA_SMEM>>>();
    proj_kernel<<<dim3(SEQ / 128, CCH / 128, BATCH), 256>>>(bp, out);
}